// round 10
// baseline (speedup 1.0000x reference)
#include <cuda_runtime.h>
#include <cuda_bf16.h>
#include <cstdint>

// ---------------------------------------------------------------------------
// Scratch (device globals; no allocation allowed)
// ---------------------------------------------------------------------------
__device__ float g_y[4096 * 1024];            // tanh(x@[W1;W2]^T + b), 16MB
__device__ __nv_bfloat16 g_wh[1024 * 512];    // [W1;W2] hi
__device__ __nv_bfloat16 g_wl[1024 * 512];    // [W1;W2] lo

static __device__ __forceinline__ uint32_t s2u(const void* p) {
    return (uint32_t)__cvta_generic_to_shared(p);
}
static __device__ __forceinline__ float frcp(float x) {
    float r;
    asm("rcp.approx.ftz.f32 %0, %1;" : "=f"(r) : "f"(x));
    return r;
}

// ---- packed f32x2 ops (Blackwell) ----
static __device__ __forceinline__ uint64_t fma2(uint64_t a, uint64_t b, uint64_t c) {
    uint64_t d;
    asm("fma.rn.f32x2 %0, %1, %2, %3;" : "=l"(d) : "l"(a), "l"(b), "l"(c));
    return d;
}
static __device__ __forceinline__ uint64_t add2(uint64_t a, uint64_t b) {
    uint64_t d;
    asm("add.rn.f32x2 %0, %1, %2;" : "=l"(d) : "l"(a), "l"(b));
    return d;
}
static __device__ __forceinline__ uint64_t mul2(uint64_t a, uint64_t b) {
    uint64_t d;
    asm("mul.rn.f32x2 %0, %1, %2;" : "=l"(d) : "l"(a), "l"(b));
    return d;
}
static __device__ __forceinline__ uint64_t bcast2(float x) {
    uint64_t d;
    asm("mov.b64 %0, {%1, %1};" : "=l"(d) : "f"(x));
    return d;
}
static __device__ __forceinline__ uint64_t pack2(float x, float y) {
    uint64_t d;
    asm("mov.b64 %0, {%1, %2};" : "=l"(d) : "f"(x), "f"(y));
    return d;
}
static __device__ __forceinline__ float2 unpack2(uint64_t v) {
    float2 r;
    asm("mov.b64 {%0, %1}, %2;" : "=f"(r.x), "=f"(r.y) : "l"(v));
    return r;
}

// ---------------------------------------------------------------------------
// Phase 0: split W1+W2 fp32 -> bf16 hi/lo, x4 vectorized (float4 in, 8B out)
// ---------------------------------------------------------------------------
__global__ __launch_bounds__(256) void split_w_kernel(
    const float* __restrict__ W1, const float* __restrict__ W2,
    __nv_bfloat16* __restrict__ dh, __nv_bfloat16* __restrict__ dl)
{
    int i = blockIdx.x * 256 + threadIdx.x;   // [0, 131072)
    int base = i * 4;
    float4 v = (base < 262144) ? *(const float4*)(W1 + base)
                               : *(const float4*)(W2 + base - 262144);
    __nv_bfloat162 h01 = __float22bfloat162_rn(make_float2(v.x, v.y));
    __nv_bfloat162 h23 = __float22bfloat162_rn(make_float2(v.z, v.w));
    float2 hf01 = __bfloat1622float2(h01);
    float2 hf23 = __bfloat1622float2(h23);
    __nv_bfloat162 l01 = __float22bfloat162_rn(make_float2(v.x - hf01.x, v.y - hf01.y));
    __nv_bfloat162 l23 = __float22bfloat162_rn(make_float2(v.z - hf23.x, v.w - hf23.y));
    uint2 hh, ll;
    hh.x = *(uint32_t*)&h01; hh.y = *(uint32_t*)&h23;
    ll.x = *(uint32_t*)&l01; ll.y = *(uint32_t*)&l23;
    *(uint2*)(dh + base) = hh;
    *(uint2*)(dl + base) = ll;
}

// ---------------------------------------------------------------------------
// Phase 1: split-bf16 GEMM on mma.sync (HMMA.16816). Unchanged (43.4us).
// ---------------------------------------------------------------------------
#define ROWB 144
#define TILEB (128 * ROWB)
#define SM_AH 0
#define SM_AL TILEB
#define SM_BH (2 * TILEB)
#define SM_BL (3 * TILEB)
#define SM_TOTAL (4 * TILEB)

#define LDM_X4(r0, r1, r2, r3, addr) \
    asm volatile("ldmatrix.sync.aligned.m8n8.x4.shared.b16 {%0,%1,%2,%3}, [%4];" \
                 : "=r"(r0), "=r"(r1), "=r"(r2), "=r"(r3) : "r"(addr))

#define MMA_BF16(c, a, b) \
    asm volatile("mma.sync.aligned.m16n8k16.row.col.f32.bf16.bf16.f32 " \
                 "{%0,%1,%2,%3}, {%4,%5,%6,%7}, {%8,%9}, {%0,%1,%2,%3};" \
                 : "+f"((c)[0]), "+f"((c)[1]), "+f"((c)[2]), "+f"((c)[3]) \
                 : "r"((a)[0]), "r"((a)[1]), "r"((a)[2]), "r"((a)[3]), \
                   "r"((b)[0]), "r"((b)[1]))

__global__ __launch_bounds__(256, 2) void gemm_tc_kernel(
    const float* __restrict__ x,
    const float* __restrict__ b1, const float* __restrict__ b2)
{
    extern __shared__ char sm[];
    const uint32_t sb = s2u(sm);
    const int tid  = threadIdx.x;
    const int wid  = tid >> 5;
    const int lane = tid & 31;

    const int mBase = blockIdx.x * 128;
    const int nBase = blockIdx.y * 128;

    const int wm = wid & 1;
    const int wn = wid >> 1;

    const int lr  = lane & 7;
    const int ls3 = (lane >> 3) & 1;
    const int ls4 = (lane >> 4) & 1;

    float acc[4][4][4];
#pragma unroll
    for (int mi = 0; mi < 4; mi++)
#pragma unroll
        for (int ni = 0; ni < 4; ni++)
#pragma unroll
            for (int f = 0; f < 4; f++) acc[mi][ni][f] = 0.0f;

    for (int kc = 0; kc < 8; kc++) {
        __syncthreads();

        float4 va[8];
#pragma unroll
        for (int t = 0; t < 8; t++) {
            int idx = tid + t * 256;
            int row = idx >> 4;
            int c4  = idx & 15;
            va[t] = *(const float4*)(x + (size_t)(mBase + row) * 512 + kc * 64 + c4 * 4);
        }
#pragma unroll
        for (int t = 0; t < 8; t++) {
            int idx  = tid + t * 256;
            int tile = idx >> 10;
            int u    = idx & 1023;
            int row  = u >> 3;
            int c16  = u & 7;
            const __nv_bfloat16* gsrc = (tile == 0 ? g_wh : g_wl) + (size_t)(nBase + row) * 512;
            *(uint4*)(sm + (2 + tile) * TILEB + row * ROWB + c16 * 16) =
                *(const uint4*)(gsrc + kc * 64 + c16 * 8);
        }
#pragma unroll
        for (int t = 0; t < 8; t++) {
            int idx = tid + t * 256;
            int row = idx >> 4;
            int c4  = idx & 15;
            uint32_t off = row * ROWB + c4 * 8;
            __nv_bfloat162 h01 = __float22bfloat162_rn(make_float2(va[t].x, va[t].y));
            __nv_bfloat162 h23 = __float22bfloat162_rn(make_float2(va[t].z, va[t].w));
            float2 hf01 = __bfloat1622float2(h01);
            float2 hf23 = __bfloat1622float2(h23);
            __nv_bfloat162 l01 = __float22bfloat162_rn(
                make_float2(va[t].x - hf01.x, va[t].y - hf01.y));
            __nv_bfloat162 l23 = __float22bfloat162_rn(
                make_float2(va[t].z - hf23.x, va[t].w - hf23.y));
            uint2 hh, ll;
            hh.x = *(uint32_t*)&h01; hh.y = *(uint32_t*)&h23;
            ll.x = *(uint32_t*)&l01; ll.y = *(uint32_t*)&l23;
            *(uint2*)(sm + SM_AH + off) = hh;
            *(uint2*)(sm + SM_AL + off) = ll;
        }
        __syncthreads();

#pragma unroll
        for (int ks = 0; ks < 4; ks++) {
            const int kb = ks * 16;
            uint32_t aoff = (uint32_t)((wm * 64 + ls3 * 8 + lr) * ROWB + (kb + ls4 * 8) * 2);
            uint32_t boff = (uint32_t)((wn * 32 + ls4 * 8 + lr) * ROWB + (kb + ls3 * 8) * 2);

            uint32_t bhf[4][2], blf[4][2];
#pragma unroll
            for (int nb = 0; nb < 2; nb++) {
                LDM_X4(bhf[2 * nb][0], bhf[2 * nb][1], bhf[2 * nb + 1][0], bhf[2 * nb + 1][1],
                       sb + SM_BH + boff + nb * 16 * ROWB);
                LDM_X4(blf[2 * nb][0], blf[2 * nb][1], blf[2 * nb + 1][0], blf[2 * nb + 1][1],
                       sb + SM_BL + boff + nb * 16 * ROWB);
            }

            uint32_t af[4][4];
#pragma unroll
            for (int mi = 0; mi < 4; mi++)
                LDM_X4(af[mi][0], af[mi][1], af[mi][2], af[mi][3],
                       sb + SM_AH + aoff + mi * 16 * ROWB);
#pragma unroll
            for (int mi = 0; mi < 4; mi++)
#pragma unroll
                for (int ni = 0; ni < 4; ni++)
                    MMA_BF16(acc[mi][ni], af[mi], bhf[ni]);
#pragma unroll
            for (int mi = 0; mi < 4; mi++)
#pragma unroll
                for (int ni = 0; ni < 4; ni++)
                    MMA_BF16(acc[mi][ni], af[mi], blf[ni]);
#pragma unroll
            for (int mi = 0; mi < 4; mi++)
                LDM_X4(af[mi][0], af[mi][1], af[mi][2], af[mi][3],
                       sb + SM_AL + aoff + mi * 16 * ROWB);
#pragma unroll
            for (int mi = 0; mi < 4; mi++)
#pragma unroll
                for (int ni = 0; ni < 4; ni++)
                    MMA_BF16(acc[mi][ni], af[mi], bhf[ni]);
        }
    }

    const float* bias = (nBase < 512) ? (b1 + nBase) : (b2 + (nBase - 512));
#pragma unroll
    for (int mi = 0; mi < 4; mi++) {
#pragma unroll
        for (int ni = 0; ni < 4; ni++) {
            int m = mBase + wm * 64 + mi * 16 + (lane >> 2);
            int nl = wn * 32 + ni * 8 + (lane & 3) * 2;
            float bv0 = __ldg(bias + nl);
            float bv1 = __ldg(bias + nl + 1);
            float2 o0, o1;
            o0.x = tanhf(acc[mi][ni][0] + bv0);
            o0.y = tanhf(acc[mi][ni][1] + bv1);
            o1.x = tanhf(acc[mi][ni][2] + bv0);
            o1.y = tanhf(acc[mi][ni][3] + bv1);
            *(float2*)(g_y + (size_t)m * 1024 + nBase + nl)       = o0;
            *(float2*)(g_y + (size_t)(m + 8) * 1024 + nBase + nl) = o1;
        }
    }
}

// ---------------------------------------------------------------------------
// Phase 2: out[b,i,j] = sum_a Wout[a]*tanh(x1[b,j,a] + x2[b,i+1,a]) + bout
// a-pair reduction with packed f32x2. p/wp stored PRE-DUPLICATED ({v,v} pairs)
// so broadcast operands load via one LDS.128 per j-pair — no mov.b64 packs.
// ---------------------------------------------------------------------------
#define ACH   64
#define STRD  68                  // floats per a-row of duplicated j data (32j*2 + 4 pad)
#define STRI  68
// s_p2 + s_wp2: ACH*STRD each; s_u: ACH*STRI; s_w: ACH
#define AT_SMEM ((3 * ACH * STRD + ACH) * 4)   // 55552 B

__global__ __launch_bounds__(256) void attn_kernel(
    const float* __restrict__ Wout,
    const float* __restrict__ bout,
    float* __restrict__ out)
{
    extern __shared__ float smf[];
    float* s_p2  = smf;                          // [ACH][STRD] duplicated pairs
    float* s_wp2 = smf + ACH * STRD;             // [ACH][STRD]
    float* s_u   = smf + 2 * ACH * STRD;         // [ACH][STRI]
    float* s_w   = s_u + ACH * STRI;             // [ACH]

    const int b  = blockIdx.z;
    const int j0 = blockIdx.x * 32;
    const int i0 = blockIdx.y * 64;

    const int tid = threadIdx.x;
    const int jg  = tid & 15;          // j = j0 + 2*jg + {0,1}
    const int ig  = tid >> 4;          // i = i0 + 4*ig + {0..3}

    const float* __restrict__ Y = g_y + (size_t)b * 128 * 1024;

    const int fa = tid & 63;
    const int fr = tid >> 6;

    int irow[16];
#pragma unroll
    for (int t = 0; t < 16; t++) {
        int r2 = i0 + fr + t * 4 + 1;
        irow[t] = (r2 > 127) ? 127 : r2;
    }

    float pr[8], ur[16];
#pragma unroll
    for (int t = 0; t < 8; t++)
        pr[t] = Y[(size_t)(j0 + fr + t * 4) * 1024 + fa];
#pragma unroll
    for (int t = 0; t < 16; t++)
        ur[t] = Y[(size_t)irow[t] * 1024 + 512 + fa];

    const uint64_t ONE2 = 0x3F8000003F800000ull;
    uint64_t acc2[2][2] = {{0ull, 0ull}, {0ull, 0ull}};

    for (int cc = 0; cc < 8; cc++) {
        const int ac = cc * ACH;
        const float w = __ldg(Wout + ac + fa);

        __syncthreads();
#pragma unroll
        for (int t = 0; t < 8; t++) {
            int r = fr + t * 4;
            float p = pr[t], wp = w * p;
            *(float2*)&s_p2 [fa * STRD + r * 2] = make_float2(p, p);
            *(float2*)&s_wp2[fa * STRD + r * 2] = make_float2(wp, wp);
        }
#pragma unroll
        for (int t = 0; t < 16; t++)
            s_u[fa * STRI + fr + t * 4] = ur[t];
        if (tid < ACH) s_w[tid] = w;
        __syncthreads();

        if (cc < 7) {
            const int ac2 = ac + ACH;
#pragma unroll
            for (int t = 0; t < 8; t++)
                pr[t] = Y[(size_t)(j0 + fr + t * 4) * 1024 + ac2 + fa];
#pragma unroll
            for (int t = 0; t < 16; t++)
                ur[t] = Y[(size_t)irow[t] * 1024 + 512 + ac2 + fa];
        }

#pragma unroll 2
        for (int a = 0; a < ACH; a += 2) {
            float2 wpair = *(const float2*)&s_w[a];
            // duplicated loads: {p_j0,p_j0,p_j1,p_j1} in one LDS.128
            ulonglong2 pA2  = *(const ulonglong2*)&s_p2 [ a      * STRD + jg * 4];
            ulonglong2 pB2  = *(const ulonglong2*)&s_p2 [(a + 1) * STRD + jg * 4];
            ulonglong2 wpA2 = *(const ulonglong2*)&s_wp2[ a      * STRD + jg * 4];
            ulonglong2 wpB2 = *(const ulonglong2*)&s_wp2[(a + 1) * STRD + jg * 4];
            ulonglong2 uA = *(const ulonglong2*)&s_u[ a      * STRI + ig * 4];
            ulonglong2 uB = *(const ulonglong2*)&s_u[(a + 1) * STRI + ig * 4];

            uint64_t pAb[2]  = {pA2.x,  pA2.y};
            uint64_t pBb[2]  = {pB2.x,  pB2.y};
            uint64_t wpAb[2] = {wpA2.x, wpA2.y};
            uint64_t wpBb[2] = {wpB2.x, wpB2.y};
            uint64_t wAb = bcast2(wpair.x);
            uint64_t wBb = bcast2(wpair.y);
            uint64_t uAp[2] = {uA.x, uA.y};
            uint64_t uBp[2] = {uB.x, uB.y};
            uint64_t wuA[2] = {mul2(wAb, uAp[0]), mul2(wAb, uAp[1])};
            uint64_t wuB[2] = {mul2(wBb, uBp[0]), mul2(wBb, uBp[1])};

#pragma unroll
            for (int j = 0; j < 2; j++)
#pragma unroll
                for (int ip = 0; ip < 2; ip++) {
                    uint64_t d1 = fma2(uAp[ip], pAb[j], ONE2);
                    uint64_t d2 = fma2(uBp[ip], pBb[j], ONE2);
                    uint64_t n1 = add2(wuA[ip], wpAb[j]);
                    uint64_t n2 = add2(wuB[ip], wpBb[j]);
                    uint64_t t  = mul2(d1, d2);
                    float2 tf = unpack2(t);
                    uint64_t r  = pack2(frcp(tf.x), frcp(tf.y));
                    uint64_t e  = mul2(n1, d2);
                    e = fma2(n2, d1, e);
                    acc2[j][ip] = fma2(e, r, acc2[j][ip]);
                }
        }
    }

    const float bo = __ldg(bout);
#pragma unroll
    for (int ip = 0; ip < 2; ip++) {
        float2 aj0 = unpack2(acc2[0][ip]);
        float2 aj1 = unpack2(acc2[1][ip]);
#pragma unroll
        for (int l = 0; l < 2; l++) {
            int i = i0 + ig * 4 + ip * 2 + l;
            if (i < 127) {
                float2 o;
                o.x = (l == 0 ? aj0.x : aj0.y) + bo;
                o.y = (l == 0 ? aj1.x : aj1.y) + bo;
                *(float2*)(out + ((size_t)b * 127 + i) * 128 + j0 + jg * 2) = o;
            }
        }
    }
}

// ---------------------------------------------------------------------------
extern "C" void kernel_launch(void* const* d_in, const int* in_sizes, int n_in,
                              void* d_out, int out_size)
{
    const float* x    = (const float*)d_in[0];
    const float* W1   = (const float*)d_in[1];
    const float* b1   = (const float*)d_in[2];
    const float* W2   = (const float*)d_in[3];
    const float* b2   = (const float*)d_in[4];
    const float* Wout = (const float*)d_in[5];
    const float* bout = (const float*)d_in[6];
    float* out = (float*)d_out;

    __nv_bfloat16 *wh, *wl;
    cudaGetSymbolAddress((void**)&wh, g_wh);
    cudaGetSymbolAddress((void**)&wl, g_wl);

    static bool attr_set = false;
    if (!attr_set) {
        cudaFuncSetAttribute(gemm_tc_kernel,
                             cudaFuncAttributeMaxDynamicSharedMemorySize, SM_TOTAL);
        cudaFuncSetAttribute(attn_kernel,
                             cudaFuncAttributeMaxDynamicSharedMemorySize, AT_SMEM);
        attr_set = true;
    }

    split_w_kernel<<<131072 / 256, 256>>>(W1, W2, wh, wl);

    gemm_tc_kernel<<<dim3(32, 8), 256, SM_TOTAL>>>(x, b1, b2);

    attn_kernel<<<dim3(4, 2, 32), 256, AT_SMEM>>>(Wout, bout, out);
}

// round 11
// speedup vs baseline: 1.7235x; 1.7235x over previous
#include <cuda_runtime.h>
#include <cuda_bf16.h>
#include <cstdint>

// ---------------------------------------------------------------------------
// Scratch (device globals; no allocation allowed)
// ---------------------------------------------------------------------------
__device__ float g_y[4096 * 1024];            // tanh(x@[W1;W2]^T + b), 16MB

static __device__ __forceinline__ uint32_t s2u(const void* p) {
    return (uint32_t)__cvta_generic_to_shared(p);
}
static __device__ __forceinline__ float frcp(float x) {
    float r;
    asm("rcp.approx.ftz.f32 %0, %1;" : "=f"(r) : "f"(x));
    return r;
}

// ---- packed f32x2 ops (Blackwell) ----
static __device__ __forceinline__ uint64_t fma2(uint64_t a, uint64_t b, uint64_t c) {
    uint64_t d;
    asm("fma.rn.f32x2 %0, %1, %2, %3;" : "=l"(d) : "l"(a), "l"(b), "l"(c));
    return d;
}
static __device__ __forceinline__ uint64_t add2(uint64_t a, uint64_t b) {
    uint64_t d;
    asm("add.rn.f32x2 %0, %1, %2;" : "=l"(d) : "l"(a), "l"(b));
    return d;
}
static __device__ __forceinline__ uint64_t mul2(uint64_t a, uint64_t b) {
    uint64_t d;
    asm("mul.rn.f32x2 %0, %1, %2;" : "=l"(d) : "l"(a), "l"(b));
    return d;
}
static __device__ __forceinline__ uint64_t bcast2(float x) {
    uint64_t d;
    asm("mov.b64 %0, {%1, %1};" : "=l"(d) : "f"(x));
    return d;
}
static __device__ __forceinline__ uint64_t pack2(float x, float y) {
    uint64_t d;
    asm("mov.b64 %0, {%1, %2};" : "=l"(d) : "f"(x), "f"(y));
    return d;
}
static __device__ __forceinline__ float2 unpack2(uint64_t v) {
    float2 r;
    asm("mov.b64 {%0, %1}, %2;" : "=f"(r.x), "=f"(r.y) : "l"(v));
    return r;
}

// ---------------------------------------------------------------------------
// Phase 1: split-bf16 GEMM on mma.sync (HMMA.16816).
//   C = xh@Wh^T + xh@Wl^T + xl@Wh^T  (fp32 accum), epilogue tanh(C + bias).
// CTA 128x128, warp 64x32, K in 8 chunks of 64 via smem, 2 CTAs/SM.
// BOTH x and W are loaded fp32 and hi/lo-split during the smem store
// (no separate split kernels at all).
// ---------------------------------------------------------------------------
#define ROWB 144
#define TILEB (128 * ROWB)
#define SM_AH 0
#define SM_AL TILEB
#define SM_BH (2 * TILEB)
#define SM_BL (3 * TILEB)
#define SM_TOTAL (4 * TILEB)

#define LDM_X4(r0, r1, r2, r3, addr) \
    asm volatile("ldmatrix.sync.aligned.m8n8.x4.shared.b16 {%0,%1,%2,%3}, [%4];" \
                 : "=r"(r0), "=r"(r1), "=r"(r2), "=r"(r3) : "r"(addr))

#define MMA_BF16(c, a, b) \
    asm volatile("mma.sync.aligned.m16n8k16.row.col.f32.bf16.bf16.f32 " \
                 "{%0,%1,%2,%3}, {%4,%5,%6,%7}, {%8,%9}, {%0,%1,%2,%3};" \
                 : "+f"((c)[0]), "+f"((c)[1]), "+f"((c)[2]), "+f"((c)[3]) \
                 : "r"((a)[0]), "r"((a)[1]), "r"((a)[2]), "r"((a)[3]), \
                   "r"((b)[0]), "r"((b)[1]))

// split a float4 into packed bf16 hi (uint2) and lo (uint2)
static __device__ __forceinline__ void split4(float4 v, uint2& hh, uint2& ll) {
    __nv_bfloat162 h01 = __float22bfloat162_rn(make_float2(v.x, v.y));
    __nv_bfloat162 h23 = __float22bfloat162_rn(make_float2(v.z, v.w));
    float2 hf01 = __bfloat1622float2(h01);
    float2 hf23 = __bfloat1622float2(h23);
    __nv_bfloat162 l01 = __float22bfloat162_rn(make_float2(v.x - hf01.x, v.y - hf01.y));
    __nv_bfloat162 l23 = __float22bfloat162_rn(make_float2(v.z - hf23.x, v.w - hf23.y));
    hh.x = *(uint32_t*)&h01; hh.y = *(uint32_t*)&h23;
    ll.x = *(uint32_t*)&l01; ll.y = *(uint32_t*)&l23;
}

__global__ __launch_bounds__(256, 2) void gemm_tc_kernel(
    const float* __restrict__ x,
    const float* __restrict__ W1, const float* __restrict__ W2,
    const float* __restrict__ b1, const float* __restrict__ b2)
{
    extern __shared__ char sm[];
    const uint32_t sb = s2u(sm);
    const int tid  = threadIdx.x;
    const int wid  = tid >> 5;
    const int lane = tid & 31;

    const int mBase = blockIdx.x * 128;
    const int nBase = blockIdx.y * 128;

    const float* __restrict__ Wsrc = (nBase < 512) ? W1 : W2;
    const int nOff = nBase & 511;

    const int wm = wid & 1;
    const int wn = wid >> 1;

    const int lr  = lane & 7;
    const int ls3 = (lane >> 3) & 1;
    const int ls4 = (lane >> 4) & 1;

    float acc[4][4][4];
#pragma unroll
    for (int mi = 0; mi < 4; mi++)
#pragma unroll
        for (int ni = 0; ni < 4; ni++)
#pragma unroll
            for (int f = 0; f < 4; f++) acc[mi][ni][f] = 0.0f;

    for (int kc = 0; kc < 8; kc++) {
        __syncthreads();

        // A: x fp32 (128 rows x 64 cols = 2048 float4), 8/thread
        float4 va[8];
#pragma unroll
        for (int t = 0; t < 8; t++) {
            int idx = tid + t * 256;
            int row = idx >> 4;
            int c4  = idx & 15;
            va[t] = *(const float4*)(x + (size_t)(mBase + row) * 512 + kc * 64 + c4 * 4);
        }
        // B: W fp32 (128 rows x 64 cols), 8/thread
        float4 vb[8];
#pragma unroll
        for (int t = 0; t < 8; t++) {
            int idx = tid + t * 256;
            int row = idx >> 4;
            int c4  = idx & 15;
            vb[t] = *(const float4*)(Wsrc + (size_t)(nOff + row) * 512 + kc * 64 + c4 * 4);
        }
        // split + store A
#pragma unroll
        for (int t = 0; t < 8; t++) {
            int idx = tid + t * 256;
            int row = idx >> 4;
            int c4  = idx & 15;
            uint32_t off = row * ROWB + c4 * 8;
            uint2 hh, ll;
            split4(va[t], hh, ll);
            *(uint2*)(sm + SM_AH + off) = hh;
            *(uint2*)(sm + SM_AL + off) = ll;
        }
        // split + store B
#pragma unroll
        for (int t = 0; t < 8; t++) {
            int idx = tid + t * 256;
            int row = idx >> 4;
            int c4  = idx & 15;
            uint32_t off = row * ROWB + c4 * 8;
            uint2 hh, ll;
            split4(vb[t], hh, ll);
            *(uint2*)(sm + SM_BH + off) = hh;
            *(uint2*)(sm + SM_BL + off) = ll;
        }
        __syncthreads();

#pragma unroll
        for (int ks = 0; ks < 4; ks++) {
            const int kb = ks * 16;
            uint32_t aoff = (uint32_t)((wm * 64 + ls3 * 8 + lr) * ROWB + (kb + ls4 * 8) * 2);
            uint32_t boff = (uint32_t)((wn * 32 + ls4 * 8 + lr) * ROWB + (kb + ls3 * 8) * 2);

            uint32_t bhf[4][2], blf[4][2];
#pragma unroll
            for (int nb = 0; nb < 2; nb++) {
                LDM_X4(bhf[2 * nb][0], bhf[2 * nb][1], bhf[2 * nb + 1][0], bhf[2 * nb + 1][1],
                       sb + SM_BH + boff + nb * 16 * ROWB);
                LDM_X4(blf[2 * nb][0], blf[2 * nb][1], blf[2 * nb + 1][0], blf[2 * nb + 1][1],
                       sb + SM_BL + boff + nb * 16 * ROWB);
            }

            uint32_t af[4][4];
#pragma unroll
            for (int mi = 0; mi < 4; mi++)
                LDM_X4(af[mi][0], af[mi][1], af[mi][2], af[mi][3],
                       sb + SM_AH + aoff + mi * 16 * ROWB);
#pragma unroll
            for (int mi = 0; mi < 4; mi++)
#pragma unroll
                for (int ni = 0; ni < 4; ni++)
                    MMA_BF16(acc[mi][ni], af[mi], bhf[ni]);
#pragma unroll
            for (int mi = 0; mi < 4; mi++)
#pragma unroll
                for (int ni = 0; ni < 4; ni++)
                    MMA_BF16(acc[mi][ni], af[mi], blf[ni]);
#pragma unroll
            for (int mi = 0; mi < 4; mi++)
                LDM_X4(af[mi][0], af[mi][1], af[mi][2], af[mi][3],
                       sb + SM_AL + aoff + mi * 16 * ROWB);
#pragma unroll
            for (int mi = 0; mi < 4; mi++)
#pragma unroll
                for (int ni = 0; ni < 4; ni++)
                    MMA_BF16(acc[mi][ni], af[mi], bhf[ni]);
        }
    }

    const float* bias = (nBase < 512) ? (b1 + nBase) : (b2 + (nBase - 512));
#pragma unroll
    for (int mi = 0; mi < 4; mi++) {
#pragma unroll
        for (int ni = 0; ni < 4; ni++) {
            int m = mBase + wm * 64 + mi * 16 + (lane >> 2);
            int nl = wn * 32 + ni * 8 + (lane & 3) * 2;
            float bv0 = __ldg(bias + nl);
            float bv1 = __ldg(bias + nl + 1);
            float2 o0, o1;
            o0.x = tanhf(acc[mi][ni][0] + bv0);
            o0.y = tanhf(acc[mi][ni][1] + bv1);
            o1.x = tanhf(acc[mi][ni][2] + bv0);
            o1.y = tanhf(acc[mi][ni][3] + bv1);
            *(float2*)(g_y + (size_t)m * 1024 + nBase + nl)       = o0;
            *(float2*)(g_y + (size_t)(m + 8) * 1024 + nBase + nl) = o1;
        }
    }
}

// ---------------------------------------------------------------------------
// Phase 2 (R9 version — measured ~55us; R10's pre-duplication regressed and
// is reverted): a-pair reduction with packed f32x2, wu rebuilt in-register.
// ---------------------------------------------------------------------------
#define ACH   64
#define STRJ  34
#define STRI  68
#define AT_SMEM ((2 * ACH * STRJ + ACH * STRI + ACH) * 4)   // 35072 B

__global__ __launch_bounds__(256) void attn_kernel(
    const float* __restrict__ Wout,
    const float* __restrict__ bout,
    float* __restrict__ out)
{
    extern __shared__ float smf[];
    float* s_p  = smf;                           // [ACH][STRJ]
    float* s_wp = smf + ACH * STRJ;              // [ACH][STRJ]
    float* s_u  = smf + 2 * ACH * STRJ;          // [ACH][STRI]
    float* s_w  = s_u + ACH * STRI;              // [ACH]

    const int b  = blockIdx.z;
    const int j0 = blockIdx.x * 32;
    const int i0 = blockIdx.y * 64;

    const int tid = threadIdx.x;
    const int jg  = tid & 15;          // j = j0 + 2*jg + {0,1}
    const int ig  = tid >> 4;          // i = i0 + 4*ig + {0..3}

    const float* __restrict__ Y = g_y + (size_t)b * 128 * 1024;

    const int fa = tid & 63;
    const int fr = tid >> 6;

    int irow[16];
#pragma unroll
    for (int t = 0; t < 16; t++) {
        int r2 = i0 + fr + t * 4 + 1;
        irow[t] = (r2 > 127) ? 127 : r2;
    }

    float pr[8], ur[16];
#pragma unroll
    for (int t = 0; t < 8; t++)
        pr[t] = Y[(size_t)(j0 + fr + t * 4) * 1024 + fa];
#pragma unroll
    for (int t = 0; t < 16; t++)
        ur[t] = Y[(size_t)irow[t] * 1024 + 512 + fa];

    const uint64_t ONE2 = 0x3F8000003F800000ull;
    uint64_t acc2[2][2] = {{0ull, 0ull}, {0ull, 0ull}};

    for (int cc = 0; cc < 8; cc++) {
        const int ac = cc * ACH;
        const float w = __ldg(Wout + ac + fa);

        __syncthreads();
#pragma unroll
        for (int t = 0; t < 8; t++) {
            int r = fr + t * 4;
            s_p [fa * STRJ + r] = pr[t];
            s_wp[fa * STRJ + r] = w * pr[t];
        }
#pragma unroll
        for (int t = 0; t < 16; t++)
            s_u[fa * STRI + fr + t * 4] = ur[t];
        if (tid < ACH) s_w[tid] = w;
        __syncthreads();

        if (cc < 7) {
            const int ac2 = ac + ACH;
#pragma unroll
            for (int t = 0; t < 8; t++)
                pr[t] = Y[(size_t)(j0 + fr + t * 4) * 1024 + ac2 + fa];
#pragma unroll
            for (int t = 0; t < 16; t++)
                ur[t] = Y[(size_t)irow[t] * 1024 + 512 + ac2 + fa];
        }

#pragma unroll 2
        for (int a = 0; a < ACH; a += 2) {
            float2 wpair = *(const float2*)&s_w[a];
            float2 pA  = *(const float2*)&s_p [ a      * STRJ + jg * 2];
            float2 pB  = *(const float2*)&s_p [(a + 1) * STRJ + jg * 2];
            float2 wpA = *(const float2*)&s_wp[ a      * STRJ + jg * 2];
            float2 wpB = *(const float2*)&s_wp[(a + 1) * STRJ + jg * 2];
            ulonglong2 uA = *(const ulonglong2*)&s_u[ a      * STRI + ig * 4];
            ulonglong2 uB = *(const ulonglong2*)&s_u[(a + 1) * STRI + ig * 4];

            uint64_t pAb[2]  = {bcast2(pA.x),  bcast2(pA.y)};
            uint64_t pBb[2]  = {bcast2(pB.x),  bcast2(pB.y)};
            uint64_t wpAb[2] = {bcast2(wpA.x), bcast2(wpA.y)};
            uint64_t wpBb[2] = {bcast2(wpB.x), bcast2(wpB.y)};
            uint64_t wAb = bcast2(wpair.x);
            uint64_t wBb = bcast2(wpair.y);
            uint64_t uAp[2] = {uA.x, uA.y};
            uint64_t uBp[2] = {uB.x, uB.y};
            uint64_t wuA[2] = {mul2(wAb, uAp[0]), mul2(wAb, uAp[1])};
            uint64_t wuB[2] = {mul2(wBb, uBp[0]), mul2(wBb, uBp[1])};

#pragma unroll
            for (int j = 0; j < 2; j++)
#pragma unroll
                for (int ip = 0; ip < 2; ip++) {
                    uint64_t d1 = fma2(uAp[ip], pAb[j], ONE2);
                    uint64_t d2 = fma2(uBp[ip], pBb[j], ONE2);
                    uint64_t n1 = add2(wuA[ip], wpAb[j]);
                    uint64_t n2 = add2(wuB[ip], wpBb[j]);
                    uint64_t t  = mul2(d1, d2);
                    float2 tf = unpack2(t);
                    uint64_t r  = pack2(frcp(tf.x), frcp(tf.y));
                    uint64_t e  = mul2(n1, d2);
                    e = fma2(n2, d1, e);
                    acc2[j][ip] = fma2(e, r, acc2[j][ip]);
                }
        }
    }

    const float bo = __ldg(bout);
#pragma unroll
    for (int ip = 0; ip < 2; ip++) {
        float2 aj0 = unpack2(acc2[0][ip]);
        float2 aj1 = unpack2(acc2[1][ip]);
#pragma unroll
        for (int l = 0; l < 2; l++) {
            int i = i0 + ig * 4 + ip * 2 + l;
            if (i < 127) {
                float2 o;
                o.x = (l == 0 ? aj0.x : aj0.y) + bo;
                o.y = (l == 0 ? aj1.x : aj1.y) + bo;
                *(float2*)(out + ((size_t)b * 127 + i) * 128 + j0 + jg * 2) = o;
            }
        }
    }
}

// ---------------------------------------------------------------------------
extern "C" void kernel_launch(void* const* d_in, const int* in_sizes, int n_in,
                              void* d_out, int out_size)
{
    const float* x    = (const float*)d_in[0];
    const float* W1   = (const float*)d_in[1];
    const float* b1   = (const float*)d_in[2];
    const float* W2   = (const float*)d_in[3];
    const float* b2   = (const float*)d_in[4];
    const float* Wout = (const float*)d_in[5];
    const float* bout = (const float*)d_in[6];
    float* out = (float*)d_out;

    static bool attr_set = false;
    if (!attr_set) {
        cudaFuncSetAttribute(gemm_tc_kernel,
                             cudaFuncAttributeMaxDynamicSharedMemorySize, SM_TOTAL);
        cudaFuncSetAttribute(attn_kernel,
                             cudaFuncAttributeMaxDynamicSharedMemorySize, AT_SMEM);
        attr_set = true;
    }

    // Phase 1: GEMM (x and W both split on the fly) + tanh epilogue
    gemm_tc_kernel<<<dim3(32, 8), 256, SM_TOTAL>>>(x, W1, W2, b1, b2);

    // Phase 2: additive attention (R9 layout)
    attn_kernel<<<dim3(4, 2, 32), 256, AT_SMEM>>>(Wout, bout, out);
}

// round 12
// speedup vs baseline: 1.7268x; 1.0019x over previous
#include <cuda_runtime.h>
#include <cuda_bf16.h>
#include <cstdint>

// ---------------------------------------------------------------------------
// Scratch (device globals; no allocation allowed)
// ---------------------------------------------------------------------------
__device__ float g_y[4096 * 1024];            // tanh(x@[W1;W2]^T + b), 16MB

static __device__ __forceinline__ uint32_t s2u(const void* p) {
    return (uint32_t)__cvta_generic_to_shared(p);
}
static __device__ __forceinline__ float frcp(float x) {
    float r;
    asm("rcp.approx.ftz.f32 %0, %1;" : "=f"(r) : "f"(x));
    return r;
}

// ---- packed f32x2 ops (Blackwell) ----
static __device__ __forceinline__ uint64_t fma2(uint64_t a, uint64_t b, uint64_t c) {
    uint64_t d;
    asm("fma.rn.f32x2 %0, %1, %2, %3;" : "=l"(d) : "l"(a), "l"(b), "l"(c));
    return d;
}
static __device__ __forceinline__ uint64_t add2(uint64_t a, uint64_t b) {
    uint64_t d;
    asm("add.rn.f32x2 %0, %1, %2;" : "=l"(d) : "l"(a), "l"(b));
    return d;
}
static __device__ __forceinline__ uint64_t mul2(uint64_t a, uint64_t b) {
    uint64_t d;
    asm("mul.rn.f32x2 %0, %1, %2;" : "=l"(d) : "l"(a), "l"(b));
    return d;
}
static __device__ __forceinline__ uint64_t bcast2(float x) {
    uint64_t d;
    asm("mov.b64 %0, {%1, %1};" : "=l"(d) : "f"(x));
    return d;
}
static __device__ __forceinline__ uint64_t pack2(float x, float y) {
    uint64_t d;
    asm("mov.b64 %0, {%1, %2};" : "=l"(d) : "f"(x), "f"(y));
    return d;
}
static __device__ __forceinline__ float2 unpack2(uint64_t v) {
    float2 r;
    asm("mov.b64 {%0, %1}, %2;" : "=f"(r.x), "=f"(r.y) : "l"(v));
    return r;
}

// ---------------------------------------------------------------------------
// Phase 1: split-bf16 GEMM on mma.sync (HMMA.16816). Unchanged from R11
// (measured ~41us): x and W both hi/lo-split during the smem store.
// ---------------------------------------------------------------------------
#define ROWB 144
#define TILEB (128 * ROWB)
#define SM_AH 0
#define SM_AL TILEB
#define SM_BH (2 * TILEB)
#define SM_BL (3 * TILEB)
#define SM_TOTAL (4 * TILEB)

#define LDM_X4(r0, r1, r2, r3, addr) \
    asm volatile("ldmatrix.sync.aligned.m8n8.x4.shared.b16 {%0,%1,%2,%3}, [%4];" \
                 : "=r"(r0), "=r"(r1), "=r"(r2), "=r"(r3) : "r"(addr))

#define MMA_BF16(c, a, b) \
    asm volatile("mma.sync.aligned.m16n8k16.row.col.f32.bf16.bf16.f32 " \
                 "{%0,%1,%2,%3}, {%4,%5,%6,%7}, {%8,%9}, {%0,%1,%2,%3};" \
                 : "+f"((c)[0]), "+f"((c)[1]), "+f"((c)[2]), "+f"((c)[3]) \
                 : "r"((a)[0]), "r"((a)[1]), "r"((a)[2]), "r"((a)[3]), \
                   "r"((b)[0]), "r"((b)[1]))

static __device__ __forceinline__ void split4(float4 v, uint2& hh, uint2& ll) {
    __nv_bfloat162 h01 = __float22bfloat162_rn(make_float2(v.x, v.y));
    __nv_bfloat162 h23 = __float22bfloat162_rn(make_float2(v.z, v.w));
    float2 hf01 = __bfloat1622float2(h01);
    float2 hf23 = __bfloat1622float2(h23);
    __nv_bfloat162 l01 = __float22bfloat162_rn(make_float2(v.x - hf01.x, v.y - hf01.y));
    __nv_bfloat162 l23 = __float22bfloat162_rn(make_float2(v.z - hf23.x, v.w - hf23.y));
    hh.x = *(uint32_t*)&h01; hh.y = *(uint32_t*)&h23;
    ll.x = *(uint32_t*)&l01; ll.y = *(uint32_t*)&l23;
}

__global__ __launch_bounds__(256, 2) void gemm_tc_kernel(
    const float* __restrict__ x,
    const float* __restrict__ W1, const float* __restrict__ W2,
    const float* __restrict__ b1, const float* __restrict__ b2)
{
    extern __shared__ char sm[];
    const uint32_t sb = s2u(sm);
    const int tid  = threadIdx.x;
    const int wid  = tid >> 5;
    const int lane = tid & 31;

    const int mBase = blockIdx.x * 128;
    const int nBase = blockIdx.y * 128;

    const float* __restrict__ Wsrc = (nBase < 512) ? W1 : W2;
    const int nOff = nBase & 511;

    const int wm = wid & 1;
    const int wn = wid >> 1;

    const int lr  = lane & 7;
    const int ls3 = (lane >> 3) & 1;
    const int ls4 = (lane >> 4) & 1;

    float acc[4][4][4];
#pragma unroll
    for (int mi = 0; mi < 4; mi++)
#pragma unroll
        for (int ni = 0; ni < 4; ni++)
#pragma unroll
            for (int f = 0; f < 4; f++) acc[mi][ni][f] = 0.0f;

    for (int kc = 0; kc < 8; kc++) {
        __syncthreads();

        float4 va[8];
#pragma unroll
        for (int t = 0; t < 8; t++) {
            int idx = tid + t * 256;
            int row = idx >> 4;
            int c4  = idx & 15;
            va[t] = *(const float4*)(x + (size_t)(mBase + row) * 512 + kc * 64 + c4 * 4);
        }
        float4 vb[8];
#pragma unroll
        for (int t = 0; t < 8; t++) {
            int idx = tid + t * 256;
            int row = idx >> 4;
            int c4  = idx & 15;
            vb[t] = *(const float4*)(Wsrc + (size_t)(nOff + row) * 512 + kc * 64 + c4 * 4);
        }
#pragma unroll
        for (int t = 0; t < 8; t++) {
            int idx = tid + t * 256;
            int row = idx >> 4;
            int c4  = idx & 15;
            uint32_t off = row * ROWB + c4 * 8;
            uint2 hh, ll;
            split4(va[t], hh, ll);
            *(uint2*)(sm + SM_AH + off) = hh;
            *(uint2*)(sm + SM_AL + off) = ll;
        }
#pragma unroll
        for (int t = 0; t < 8; t++) {
            int idx = tid + t * 256;
            int row = idx >> 4;
            int c4  = idx & 15;
            uint32_t off = row * ROWB + c4 * 8;
            uint2 hh, ll;
            split4(vb[t], hh, ll);
            *(uint2*)(sm + SM_BH + off) = hh;
            *(uint2*)(sm + SM_BL + off) = ll;
        }
        __syncthreads();

#pragma unroll
        for (int ks = 0; ks < 4; ks++) {
            const int kb = ks * 16;
            uint32_t aoff = (uint32_t)((wm * 64 + ls3 * 8 + lr) * ROWB + (kb + ls4 * 8) * 2);
            uint32_t boff = (uint32_t)((wn * 32 + ls4 * 8 + lr) * ROWB + (kb + ls3 * 8) * 2);

            uint32_t bhf[4][2], blf[4][2];
#pragma unroll
            for (int nb = 0; nb < 2; nb++) {
                LDM_X4(bhf[2 * nb][0], bhf[2 * nb][1], bhf[2 * nb + 1][0], bhf[2 * nb + 1][1],
                       sb + SM_BH + boff + nb * 16 * ROWB);
                LDM_X4(blf[2 * nb][0], blf[2 * nb][1], blf[2 * nb + 1][0], blf[2 * nb + 1][1],
                       sb + SM_BL + boff + nb * 16 * ROWB);
            }

            uint32_t af[4][4];
#pragma unroll
            for (int mi = 0; mi < 4; mi++)
                LDM_X4(af[mi][0], af[mi][1], af[mi][2], af[mi][3],
                       sb + SM_AH + aoff + mi * 16 * ROWB);
#pragma unroll
            for (int mi = 0; mi < 4; mi++)
#pragma unroll
                for (int ni = 0; ni < 4; ni++)
                    MMA_BF16(acc[mi][ni], af[mi], bhf[ni]);
#pragma unroll
            for (int mi = 0; mi < 4; mi++)
#pragma unroll
                for (int ni = 0; ni < 4; ni++)
                    MMA_BF16(acc[mi][ni], af[mi], blf[ni]);
#pragma unroll
            for (int mi = 0; mi < 4; mi++)
                LDM_X4(af[mi][0], af[mi][1], af[mi][2], af[mi][3],
                       sb + SM_AL + aoff + mi * 16 * ROWB);
#pragma unroll
            for (int mi = 0; mi < 4; mi++)
#pragma unroll
                for (int ni = 0; ni < 4; ni++)
                    MMA_BF16(acc[mi][ni], af[mi], bhf[ni]);
        }
    }

    const float* bias = (nBase < 512) ? (b1 + nBase) : (b2 + (nBase - 512));
#pragma unroll
    for (int mi = 0; mi < 4; mi++) {
#pragma unroll
        for (int ni = 0; ni < 4; ni++) {
            int m = mBase + wm * 64 + mi * 16 + (lane >> 2);
            int nl = wn * 32 + ni * 8 + (lane & 3) * 2;
            float bv0 = __ldg(bias + nl);
            float bv1 = __ldg(bias + nl + 1);
            float2 o0, o1;
            o0.x = tanhf(acc[mi][ni][0] + bv0);
            o0.y = tanhf(acc[mi][ni][1] + bv1);
            o1.x = tanhf(acc[mi][ni][2] + bv0);
            o1.y = tanhf(acc[mi][ni][3] + bv1);
            *(float2*)(g_y + (size_t)m * 1024 + nBase + nl)       = o0;
            *(float2*)(g_y + (size_t)(m + 8) * 1024 + nBase + nl) = o1;
        }
    }
}

// ---------------------------------------------------------------------------
// Phase 2: a-pair reduction with packed f32x2 (R9 inner loop). Registers cut
// (no prefetch arrays, no irow array) + __launch_bounds__(256,3) so three
// CTAs co-reside per SM: 6 warps/SMSP fill the dependency-chain stalls that
// held issue at 50% with 2 CTAs/SM. Fill latency is covered by co-residents.
// ---------------------------------------------------------------------------
#define ACH   64
#define STRJ  34
#define STRI  68
#define AT_SMEM ((2 * ACH * STRJ + ACH * STRI + ACH) * 4)   // 35072 B

__global__ __launch_bounds__(256, 3) void attn_kernel(
    const float* __restrict__ Wout,
    const float* __restrict__ bout,
    float* __restrict__ out)
{
    extern __shared__ float smf[];
    float* s_p  = smf;                           // [ACH][STRJ]
    float* s_wp = smf + ACH * STRJ;              // [ACH][STRJ]
    float* s_u  = smf + 2 * ACH * STRJ;          // [ACH][STRI]
    float* s_w  = s_u + ACH * STRI;              // [ACH]

    const int b  = blockIdx.z;
    const int j0 = blockIdx.x * 32;
    const int i0 = blockIdx.y * 64;

    const int tid = threadIdx.x;
    const int jg  = tid & 15;          // j = j0 + 2*jg + {0,1}
    const int ig  = tid >> 4;          // i = i0 + 4*ig + {0..3}

    const float* __restrict__ Y = g_y + (size_t)b * 128 * 1024;

    const int fa = tid & 63;
    const int fr = tid >> 6;

    const uint64_t ONE2 = 0x3F8000003F800000ull;
    uint64_t acc2[2][2] = {{0ull, 0ull}, {0ull, 0ull}};

    for (int cc = 0; cc < 8; cc++) {
        const int ac = cc * ACH;
        const float w = __ldg(Wout + ac + fa);

        __syncthreads();
        // fill: direct loads; co-resident CTAs cover the LDG latency
#pragma unroll
        for (int t = 0; t < 8; t++) {
            int r = fr + t * 4;
            float p = Y[(size_t)(j0 + r) * 1024 + ac + fa];
            s_p [fa * STRJ + r] = p;
            s_wp[fa * STRJ + r] = w * p;
        }
#pragma unroll
        for (int t = 0; t < 16; t++) {
            int r  = fr + t * 4;
            int r2 = i0 + r + 1;
            r2 = (r2 > 127) ? 127 : r2;
            s_u[fa * STRI + r] = Y[(size_t)r2 * 1024 + 512 + ac + fa];
        }
        if (tid < ACH) s_w[tid] = w;
        __syncthreads();

#pragma unroll 2
        for (int a = 0; a < ACH; a += 2) {
            float2 wpair = *(const float2*)&s_w[a];
            float2 pA  = *(const float2*)&s_p [ a      * STRJ + jg * 2];
            float2 pB  = *(const float2*)&s_p [(a + 1) * STRJ + jg * 2];
            float2 wpA = *(const float2*)&s_wp[ a      * STRJ + jg * 2];
            float2 wpB = *(const float2*)&s_wp[(a + 1) * STRJ + jg * 2];
            ulonglong2 uA = *(const ulonglong2*)&s_u[ a      * STRI + ig * 4];
            ulonglong2 uB = *(const ulonglong2*)&s_u[(a + 1) * STRI + ig * 4];

            uint64_t pAb[2]  = {bcast2(pA.x),  bcast2(pA.y)};
            uint64_t pBb[2]  = {bcast2(pB.x),  bcast2(pB.y)};
            uint64_t wpAb[2] = {bcast2(wpA.x), bcast2(wpA.y)};
            uint64_t wpBb[2] = {bcast2(wpB.x), bcast2(wpB.y)};
            uint64_t wAb = bcast2(wpair.x);
            uint64_t wBb = bcast2(wpair.y);
            uint64_t uAp[2] = {uA.x, uA.y};
            uint64_t uBp[2] = {uB.x, uB.y};
            uint64_t wuA[2] = {mul2(wAb, uAp[0]), mul2(wAb, uAp[1])};
            uint64_t wuB[2] = {mul2(wBb, uBp[0]), mul2(wBb, uBp[1])};

#pragma unroll
            for (int j = 0; j < 2; j++)
#pragma unroll
                for (int ip = 0; ip < 2; ip++) {
                    uint64_t d1 = fma2(uAp[ip], pAb[j], ONE2);
                    uint64_t d2 = fma2(uBp[ip], pBb[j], ONE2);
                    uint64_t n1 = add2(wuA[ip], wpAb[j]);
                    uint64_t n2 = add2(wuB[ip], wpBb[j]);
                    uint64_t t  = mul2(d1, d2);
                    float2 tf = unpack2(t);
                    uint64_t r  = pack2(frcp(tf.x), frcp(tf.y));
                    uint64_t e  = mul2(n1, d2);
                    e = fma2(n2, d1, e);
                    acc2[j][ip] = fma2(e, r, acc2[j][ip]);
                }
        }
    }

    const float bo = __ldg(bout);
#pragma unroll
    for (int ip = 0; ip < 2; ip++) {
        float2 aj0 = unpack2(acc2[0][ip]);
        float2 aj1 = unpack2(acc2[1][ip]);
#pragma unroll
        for (int l = 0; l < 2; l++) {
            int i = i0 + ig * 4 + ip * 2 + l;
            if (i < 127) {
                float2 o;
                o.x = (l == 0 ? aj0.x : aj0.y) + bo;
                o.y = (l == 0 ? aj1.x : aj1.y) + bo;
                *(float2*)(out + ((size_t)b * 127 + i) * 128 + j0 + jg * 2) = o;
            }
        }
    }
}

// ---------------------------------------------------------------------------
extern "C" void kernel_launch(void* const* d_in, const int* in_sizes, int n_in,
                              void* d_out, int out_size)
{
    const float* x    = (const float*)d_in[0];
    const float* W1   = (const float*)d_in[1];
    const float* b1   = (const float*)d_in[2];
    const float* W2   = (const float*)d_in[3];
    const float* b2   = (const float*)d_in[4];
    const float* Wout = (const float*)d_in[5];
    const float* bout = (const float*)d_in[6];
    float* out = (float*)d_out;

    static bool attr_set = false;
    if (!attr_set) {
        cudaFuncSetAttribute(gemm_tc_kernel,
                             cudaFuncAttributeMaxDynamicSharedMemorySize, SM_TOTAL);
        cudaFuncSetAttribute(attn_kernel,
                             cudaFuncAttributeMaxDynamicSharedMemorySize, AT_SMEM);
        attr_set = true;
    }

    gemm_tc_kernel<<<dim3(32, 8), 256, SM_TOTAL>>>(x, W1, W2, b1, b2);

    attn_kernel<<<dim3(4, 2, 32), 256, AT_SMEM>>>(Wout, bout, out);
}